// round 2
// baseline (speedup 1.0000x reference)
#include <cuda_runtime.h>
#include <math.h>

// Problem constants (fixed by the dataset)
#define S_TOK   4096      // 4*32*32
#define DIM     1536
#define HEADS   12
#define HD      128
#define HD_HALF 64
#define EPS_RMS 1e-6f

// ---------------------------------------------------------------------------
// Scratch (no cudaMalloc allowed): device globals
// ---------------------------------------------------------------------------
__device__ float g_cos[S_TOK * HD_HALF];
__device__ float g_sin[S_TOK * HD_HALF];
__device__ float g_q[S_TOK * DIM];
__device__ float g_k[S_TOK * DIM];
__device__ float g_v[S_TOK * DIM];
__device__ float g_o[S_TOK * DIM];

// ---------------------------------------------------------------------------
// RoPE cos/sin tables:  pos -> (f,h,w); 64 half-dim angles per pos
//   i in [0,22): freqs[f][i]; [22,43): freqs[h][i]; [43,64): freqs[w][i]
// ---------------------------------------------------------------------------
__global__ void rope_table_kernel(const float* __restrict__ freqs)
{
    int idx = blockIdx.x * blockDim.x + threadIdx.x;   // pos*64 + i
    if (idx >= S_TOK * HD_HALF) return;
    int pos = idx >> 6;
    int i   = idx & 63;
    int f = pos >> 10;          // / (32*32)
    int h = (pos >> 5) & 31;
    int w = pos & 31;
    int row = (i < 22) ? f : ((i < 43) ? h : w);
    float ang = freqs[row * HD_HALF + i];
    g_cos[idx] = cosf(ang);
    g_sin[idx] = sinf(ang);
}

// ---------------------------------------------------------------------------
// SGEMM: C[M,N] = A[M,K] @ W[N,K]^T + bias[N]
// 128x128 block tile, BK=8, 256 threads, 8x8 per thread (strided mapping)
// ---------------------------------------------------------------------------
#define GBM 128
#define GBN 128
#define GBK 8

__global__ __launch_bounds__(256, 2)
void sgemm_bias_kernel(const float* __restrict__ A,
                       const float* __restrict__ W,
                       const float* __restrict__ bias,
                       float* __restrict__ C,
                       int M, int N, int K)
{
    __shared__ float As[GBK][GBM];
    __shared__ float Bs[GBK][GBN];

    const int tid = threadIdx.x;
    const int m0 = blockIdx.y * GBM;
    const int n0 = blockIdx.x * GBN;
    const int ty = tid >> 4;          // 0..15
    const int tx = tid & 15;          // 0..15

    const int lrow = tid >> 1;        // 0..127
    const int lk   = (tid & 1) * 4;   // 0 or 4

    const float* Aptr = A + (size_t)(m0 + lrow) * K + lk;
    const float* Wptr = W + (size_t)(n0 + lrow) * K + lk;

    float acc[8][8];
#pragma unroll
    for (int i = 0; i < 8; i++)
#pragma unroll
        for (int j = 0; j < 8; j++) acc[i][j] = 0.f;

    for (int k0 = 0; k0 < K; k0 += GBK) {
        float4 av = *(const float4*)(Aptr + k0);
        float4 bv = *(const float4*)(Wptr + k0);
        As[lk + 0][lrow] = av.x;  As[lk + 1][lrow] = av.y;
        As[lk + 2][lrow] = av.z;  As[lk + 3][lrow] = av.w;
        Bs[lk + 0][lrow] = bv.x;  Bs[lk + 1][lrow] = bv.y;
        Bs[lk + 2][lrow] = bv.z;  Bs[lk + 3][lrow] = bv.w;
        __syncthreads();

#pragma unroll
        for (int kk = 0; kk < GBK; kk++) {
            float af[8], bf[8];
#pragma unroll
            for (int i = 0; i < 8; i++) af[i] = As[kk][ty + 16 * i];
#pragma unroll
            for (int j = 0; j < 8; j++) bf[j] = Bs[kk][tx + 16 * j];
#pragma unroll
            for (int i = 0; i < 8; i++)
#pragma unroll
                for (int j = 0; j < 8; j++)
                    acc[i][j] = fmaf(af[i], bf[j], acc[i][j]);
        }
        __syncthreads();
    }

#pragma unroll
    for (int i = 0; i < 8; i++) {
        int m = m0 + ty + 16 * i;
#pragma unroll
        for (int j = 0; j < 8; j++) {
            int n = n0 + tx + 16 * j;
            C[(size_t)m * N + n] = acc[i][j] + bias[n];
        }
    }
}

// ---------------------------------------------------------------------------
// Fused RMSNorm(g) + RoPE for q and k, one block per token (256 threads)
// ---------------------------------------------------------------------------
__device__ __forceinline__ void norm_rope_row(float* __restrict__ row,
                                              const float* __restrict__ g,
                                              int s, float* red, float* rn_s)
{
    const int tid = threadIdx.x;
    float ss = 0.f;
#pragma unroll
    for (int e = tid; e < DIM; e += 256) {
        float v = row[e];
        ss += v * v;
    }
#pragma unroll
    for (int off = 16; off > 0; off >>= 1)
        ss += __shfl_xor_sync(0xffffffffu, ss, off);
    if ((tid & 31) == 0) red[tid >> 5] = ss;
    __syncthreads();
    if (tid == 0) {
        float t = 0.f;
#pragma unroll
        for (int wgi = 0; wgi < 8; wgi++) t += red[wgi];
        *rn_s = rsqrtf(t * (1.0f / DIM) + EPS_RMS);
    }
    __syncthreads();
    float rn = *rn_s;

    // 768 pairs per row; apply gain + rope
    for (int p = tid; p < DIM / 2; p += 256) {
        int i = p & 63;  // half-dim index within head
        float c  = g_cos[s * HD_HALF + i];
        float sn = g_sin[s * HD_HALF + i];
        float xe = row[2 * p]     * rn * g[2 * p];
        float xo = row[2 * p + 1] * rn * g[2 * p + 1];
        row[2 * p]     = xe * c - xo * sn;
        row[2 * p + 1] = xe * sn + xo * c;
    }
    __syncthreads();
}

__global__ __launch_bounds__(256)
void norm_rope_kernel(const float* __restrict__ gq, const float* __restrict__ gk)
{
    __shared__ float red[8];
    __shared__ float rn_s;
    int s = blockIdx.x;
    norm_rope_row(g_q + (size_t)s * DIM, gq, s, red, &rn_s);
    norm_rope_row(g_k + (size_t)s * DIM, gk, s, red, &rn_s);
}

// ---------------------------------------------------------------------------
// Flash attention (fp32): per block one (head, 64-query tile)
//   Q/K stored d-major with +1 pad (conflict-free), P staged in smem.
//   Thread (ty,tx) owns rows 4*ty+i, score cols tx+16n, out cols tx+16m.
// ---------------------------------------------------------------------------
#define FBQ 64
#define FBK 64
#define QK_STRIDE 65      // padded rows-per-d

// smem floats: Qst 128*65 + Kst 128*65 + Vs 64*128 + Ps 64*64
#define FLASH_SMEM_FLOATS (128 * QK_STRIDE * 2 + FBK * HD + FBQ * FBK)
#define FLASH_SMEM_BYTES  (FLASH_SMEM_FLOATS * 4)

__global__ __launch_bounds__(256)
void flash_kernel()
{
    extern __shared__ float sm[];
    float* Qst = sm;                             // [128][65]
    float* Kst = Qst + 128 * QK_STRIDE;          // [128][65]
    float* Vs  = Kst + 128 * QK_STRIDE;          // [64][128]
    float* Ps  = Vs + FBK * HD;                  // [64][64]

    const int h  = blockIdx.y;
    const int q0 = blockIdx.x * FBQ;
    const int tid = threadIdx.x;
    const int ty = tid >> 4;       // 0..15 -> rows 4*ty..4*ty+3
    const int tx = tid & 15;

    // Load Q tile (d-major, padded)
    for (int idx = tid; idx < FBQ * HD; idx += 256) {
        int r = idx >> 7, d = idx & 127;
        Qst[d * QK_STRIDE + r] = g_q[(size_t)(q0 + r) * DIM + h * HD + d];
    }

    float m[4], l[4], acc[4][8];
#pragma unroll
    for (int i = 0; i < 4; i++) {
        m[i] = -1e30f;
        l[i] = 0.f;
#pragma unroll
        for (int mm = 0; mm < 8; mm++) acc[i][mm] = 0.f;
    }

    const float scale = 0.08838834764831845f;  // 1/sqrt(128)

    for (int k0 = 0; k0 < S_TOK; k0 += FBK) {
        __syncthreads();   // protects Q load (first iter) and K/V/P reuse
        for (int idx = tid; idx < FBK * HD; idx += 256) {
            int r = idx >> 7, d = idx & 127;
            float kvk = g_k[(size_t)(k0 + r) * DIM + h * HD + d];
            float kvv = g_v[(size_t)(k0 + r) * DIM + h * HD + d];
            Kst[d * QK_STRIDE + r] = kvk;
            Vs[r * HD + d] = kvv;
        }
        __syncthreads();

        // scores s4[i][n] = Q[4ty+i] . K[tx+16n]
        float s4[4][4];
#pragma unroll
        for (int i = 0; i < 4; i++)
#pragma unroll
            for (int n = 0; n < 4; n++) s4[i][n] = 0.f;

#pragma unroll 4
        for (int d = 0; d < HD; d++) {
            float a[4], b[4];
#pragma unroll
            for (int i = 0; i < 4; i++) a[i] = Qst[d * QK_STRIDE + 4 * ty + i];
#pragma unroll
            for (int n = 0; n < 4; n++) b[n] = Kst[d * QK_STRIDE + tx + 16 * n];
#pragma unroll
            for (int i = 0; i < 4; i++)
#pragma unroll
                for (int n = 0; n < 4; n++)
                    s4[i][n] = fmaf(a[i], b[n], s4[i][n]);
        }

        // online softmax per row (replicated across the 16 tx lanes)
#pragma unroll
        for (int i = 0; i < 4; i++) {
            float mx = -1e30f;
#pragma unroll
            for (int n = 0; n < 4; n++) {
                s4[i][n] *= scale;
                mx = fmaxf(mx, s4[i][n]);
            }
#pragma unroll
            for (int off = 8; off > 0; off >>= 1)
                mx = fmaxf(mx, __shfl_xor_sync(0xffffffffu, mx, off));
            float mnew = fmaxf(m[i], mx);
            float sum = 0.f;
            float pv[4];
#pragma unroll
            for (int n = 0; n < 4; n++) {
                pv[n] = __expf(s4[i][n] - mnew);
                sum += pv[n];
            }
#pragma unroll
            for (int off = 8; off > 0; off >>= 1)
                sum += __shfl_xor_sync(0xffffffffu, sum, off);
            float alpha = __expf(m[i] - mnew);
            l[i] = l[i] * alpha + sum;
            m[i] = mnew;
#pragma unroll
            for (int mm = 0; mm < 8; mm++) acc[i][mm] *= alpha;
#pragma unroll
            for (int n = 0; n < 4; n++)
                Ps[(4 * ty + i) * FBK + tx + 16 * n] = pv[n];
        }
        __syncthreads();

        // acc += P . V
#pragma unroll 4
        for (int j = 0; j < FBK; j++) {
            float p[4], vv[8];
#pragma unroll
            for (int i = 0; i < 4; i++) p[i] = Ps[(4 * ty + i) * FBK + j];
#pragma unroll
            for (int mm = 0; mm < 8; mm++) vv[mm] = Vs[j * HD + tx + 16 * mm];
#pragma unroll
            for (int i = 0; i < 4; i++)
#pragma unroll
                for (int mm = 0; mm < 8; mm++)
                    acc[i][mm] = fmaf(p[i], vv[mm], acc[i][mm]);
        }
    }

    // epilogue: divide by l and store
#pragma unroll
    for (int i = 0; i < 4; i++) {
        float inv = 1.0f / l[i];
        int r = q0 + 4 * ty + i;
#pragma unroll
        for (int mm = 0; mm < 8; mm++)
            g_o[(size_t)r * DIM + h * HD + tx + 16 * mm] = acc[i][mm] * inv;
    }
}

// ---------------------------------------------------------------------------
// kernel_launch
// Inputs: 0 x, 1 seq_lens, 2 grid_sizes, 3 freqs, [4 t], Wq, bq, Wk, bk,
//         Wv, bv, Wo, bo, gq, gk
// ---------------------------------------------------------------------------
extern "C" void kernel_launch(void* const* d_in, const int* in_sizes, int n_in,
                              void* d_out, int out_size)
{
    const float* x     = (const float*)d_in[0];
    const float* freqs = (const float*)d_in[3];

    // t (python scalar) may or may not occupy a slot; detect Wq by size
    int wi = (in_sizes[4] == DIM * DIM) ? 4 : 5;
    const float* Wq = (const float*)d_in[wi + 0];
    const float* bq = (const float*)d_in[wi + 1];
    const float* Wk = (const float*)d_in[wi + 2];
    const float* bk = (const float*)d_in[wi + 3];
    const float* Wv = (const float*)d_in[wi + 4];
    const float* bv = (const float*)d_in[wi + 5];
    const float* Wo = (const float*)d_in[wi + 6];
    const float* bo = (const float*)d_in[wi + 7];
    const float* gq = (const float*)d_in[wi + 8];
    const float* gk = (const float*)d_in[wi + 9];

    float* out = (float*)d_out;

    float *dq, *dk, *dv, *dob;
    cudaGetSymbolAddress((void**)&dq,  g_q);
    cudaGetSymbolAddress((void**)&dk,  g_k);
    cudaGetSymbolAddress((void**)&dv,  g_v);
    cudaGetSymbolAddress((void**)&dob, g_o);

    // 1. RoPE tables
    rope_table_kernel<<<(S_TOK * HD_HALF + 255) / 256, 256>>>(freqs);

    // 2. q/k/v projections
    dim3 ggrid(DIM / GBN, S_TOK / GBM);
    sgemm_bias_kernel<<<ggrid, 256>>>(x, Wq, bq, dq, S_TOK, DIM, DIM);
    sgemm_bias_kernel<<<ggrid, 256>>>(x, Wk, bk, dk, S_TOK, DIM, DIM);
    sgemm_bias_kernel<<<ggrid, 256>>>(x, Wv, bv, dv, S_TOK, DIM, DIM);

    // 3. RMSNorm + RoPE on q and k
    norm_rope_kernel<<<S_TOK, 256>>>(gq, gk);

    // 4. flash attention
    cudaFuncSetAttribute(flash_kernel,
                         cudaFuncAttributeMaxDynamicSharedMemorySize,
                         FLASH_SMEM_BYTES);
    dim3 fgrid(S_TOK / FBQ, HEADS);
    flash_kernel<<<fgrid, 256, FLASH_SMEM_BYTES>>>();

    // 5. output projection -> d_out
    sgemm_bias_kernel<<<ggrid, 256>>>(dob, Wo, bo, out, S_TOK, DIM, DIM);

    (void)in_sizes; (void)n_in; (void)out_size;
}

// round 3
// speedup vs baseline: 3.3475x; 3.3475x over previous
#include <cuda_runtime.h>
#include <math.h>
#include <stdint.h>

// Problem constants (fixed by the dataset)
#define S_TOK   4096      // 4*32*32
#define DIM     1536
#define HEADS   12
#define HD      128
#define HD_HALF 64
#define EPS_RMS 1e-6f

// ---------------------------------------------------------------------------
// Scratch (no cudaMalloc allowed): device globals
// ---------------------------------------------------------------------------
__device__ float g_cos[S_TOK * HD_HALF];
__device__ float g_sin[S_TOK * HD_HALF];
__device__ float g_q[S_TOK * DIM];
__device__ float g_k[S_TOK * DIM];
__device__ float g_v[S_TOK * DIM];
__device__ float g_o[S_TOK * DIM];

// ---------------------------------------------------------------------------
// tf32 helpers
// ---------------------------------------------------------------------------
__device__ __forceinline__ uint32_t f2tf32(float f) {
    uint32_t r;
    asm("cvt.rna.tf32.f32 %0, %1;\n" : "=r"(r) : "f"(f));
    return r;
}

__device__ __forceinline__ void mma_tf32(float* c, const uint32_t* a, const uint32_t* b) {
    asm volatile(
        "mma.sync.aligned.m16n8k8.row.col.f32.tf32.tf32.f32 "
        "{%0,%1,%2,%3}, {%4,%5,%6,%7}, {%8,%9}, {%0,%1,%2,%3};\n"
        : "+f"(c[0]), "+f"(c[1]), "+f"(c[2]), "+f"(c[3])
        : "r"(a[0]), "r"(a[1]), "r"(a[2]), "r"(a[3]),
          "r"(b[0]), "r"(b[1]));
}

// ---------------------------------------------------------------------------
// RoPE cos/sin tables
// ---------------------------------------------------------------------------
__global__ void rope_table_kernel(const float* __restrict__ freqs)
{
    int idx = blockIdx.x * blockDim.x + threadIdx.x;   // pos*64 + i
    if (idx >= S_TOK * HD_HALF) return;
    int pos = idx >> 6;
    int i   = idx & 63;
    int f = pos >> 10;
    int h = (pos >> 5) & 31;
    int w = pos & 31;
    int row = (i < 22) ? f : ((i < 43) ? h : w);
    float ang = freqs[row * HD_HALF + i];
    g_cos[idx] = cosf(ang);
    g_sin[idx] = sinf(ang);
}

// ---------------------------------------------------------------------------
// TF32 tensor-core GEMM: C[M,N] = A[M,K] @ W[N,K]^T + bias[N]
// 128x128x32 block tiles, 8 warps (2x4), warp tile 64x32, m16n8k8 mma
// ---------------------------------------------------------------------------
#define GBM 128
#define GBN 128
#define GBK 32
#define GST 36     // smem row stride (pad): bank = (4*row + col) % 32 -> conflict-free frags

__global__ __launch_bounds__(256)
void gemm_tf32_kernel(const float* __restrict__ A,
                      const float* __restrict__ W,
                      const float* __restrict__ bias,
                      float* __restrict__ C,
                      int M, int N, int K)
{
    __shared__ uint32_t As[GBM * GST];
    __shared__ uint32_t Bs[GBN * GST];

    const int tid  = threadIdx.x;
    const int lane = tid & 31;
    const int warp = tid >> 5;
    const int wm   = (warp >> 2) * 64;   // warp M offset within block
    const int wn   = (warp & 3) * 32;    // warp N offset within block
    const int g    = lane >> 2;          // group id 0..7
    const int q    = lane & 3;           // thread in group 0..3

    const int m0 = blockIdx.y * GBM;
    const int n0 = blockIdx.x * GBN;

    const int lrow = tid >> 1;           // 0..127
    const int lcol = (tid & 1) * 16;     // 0 or 16

    float acc[4][4][4];
#pragma unroll
    for (int mi = 0; mi < 4; mi++)
#pragma unroll
        for (int ni = 0; ni < 4; ni++)
#pragma unroll
            for (int j = 0; j < 4; j++) acc[mi][ni][j] = 0.f;

    const float* Ap = A + (size_t)(m0 + lrow) * K + lcol;
    const float* Wp = W + (size_t)(n0 + lrow) * K + lcol;

    for (int k0 = 0; k0 < K; k0 += GBK) {
        __syncthreads();
#pragma unroll
        for (int i = 0; i < 4; i++) {
            float4 av = *(const float4*)(Ap + k0 + 4 * i);
            float4 bv = *(const float4*)(Wp + k0 + 4 * i);
            int c = lcol + 4 * i;
            As[lrow * GST + c + 0] = f2tf32(av.x);
            As[lrow * GST + c + 1] = f2tf32(av.y);
            As[lrow * GST + c + 2] = f2tf32(av.z);
            As[lrow * GST + c + 3] = f2tf32(av.w);
            Bs[lrow * GST + c + 0] = f2tf32(bv.x);
            Bs[lrow * GST + c + 1] = f2tf32(bv.y);
            Bs[lrow * GST + c + 2] = f2tf32(bv.z);
            Bs[lrow * GST + c + 3] = f2tf32(bv.w);
        }
        __syncthreads();

#pragma unroll
        for (int kk = 0; kk < GBK; kk += 8) {
            uint32_t af[4][4], bf[4][2];
#pragma unroll
            for (int mi = 0; mi < 4; mi++) {
                int r = wm + mi * 16;
                af[mi][0] = As[(r + g)     * GST + kk + q];
                af[mi][1] = As[(r + g + 8) * GST + kk + q];
                af[mi][2] = As[(r + g)     * GST + kk + q + 4];
                af[mi][3] = As[(r + g + 8) * GST + kk + q + 4];
            }
#pragma unroll
            for (int ni = 0; ni < 4; ni++) {
                int r = wn + ni * 8 + g;
                bf[ni][0] = Bs[r * GST + kk + q];
                bf[ni][1] = Bs[r * GST + kk + q + 4];
            }
#pragma unroll
            for (int mi = 0; mi < 4; mi++)
#pragma unroll
                for (int ni = 0; ni < 4; ni++)
                    mma_tf32(acc[mi][ni], af[mi], bf[ni]);
        }
    }

    // epilogue: bias + store (float2)
#pragma unroll
    for (int mi = 0; mi < 4; mi++) {
        int row0 = m0 + wm + mi * 16 + g;
#pragma unroll
        for (int ni = 0; ni < 4; ni++) {
            int col = n0 + wn + ni * 8 + 2 * q;
            float b0 = bias[col], b1 = bias[col + 1];
            float2 v0 = make_float2(acc[mi][ni][0] + b0, acc[mi][ni][1] + b1);
            float2 v1 = make_float2(acc[mi][ni][2] + b0, acc[mi][ni][3] + b1);
            *(float2*)(C + (size_t)row0 * N + col)       = v0;
            *(float2*)(C + (size_t)(row0 + 8) * N + col) = v1;
        }
    }
}

// ---------------------------------------------------------------------------
// Fused RMSNorm(g) + RoPE for q and k (one block per token)
// ---------------------------------------------------------------------------
__device__ __forceinline__ void norm_rope_row(float* __restrict__ row,
                                              const float* __restrict__ g,
                                              int s, float* red, float* rn_s)
{
    const int tid = threadIdx.x;
    float ss = 0.f;
#pragma unroll
    for (int e = tid; e < DIM; e += 256) {
        float v = row[e];
        ss += v * v;
    }
#pragma unroll
    for (int off = 16; off > 0; off >>= 1)
        ss += __shfl_xor_sync(0xffffffffu, ss, off);
    if ((tid & 31) == 0) red[tid >> 5] = ss;
    __syncthreads();
    if (tid == 0) {
        float t = 0.f;
#pragma unroll
        for (int wgi = 0; wgi < 8; wgi++) t += red[wgi];
        *rn_s = rsqrtf(t * (1.0f / DIM) + EPS_RMS);
    }
    __syncthreads();
    float rn = *rn_s;

    for (int p = tid; p < DIM / 2; p += 256) {
        int i = p & 63;
        float c  = g_cos[s * HD_HALF + i];
        float sn = g_sin[s * HD_HALF + i];
        float xe = row[2 * p]     * rn * g[2 * p];
        float xo = row[2 * p + 1] * rn * g[2 * p + 1];
        row[2 * p]     = xe * c - xo * sn;
        row[2 * p + 1] = xe * sn + xo * c;
    }
    __syncthreads();
}

__global__ __launch_bounds__(256)
void norm_rope_kernel(const float* __restrict__ gq, const float* __restrict__ gk)
{
    __shared__ float red[8];
    __shared__ float rn_s;
    int s = blockIdx.x;
    norm_rope_row(g_q + (size_t)s * DIM, gq, s, red, &rn_s);
    norm_rope_row(g_k + (size_t)s * DIM, gk, s, red, &rn_s);
}

// ---------------------------------------------------------------------------
// Flash attention, tf32 tensor cores.
// Block: 256 threads (8 warps), 128 query rows (warp w owns rows 16w..16w+15),
// 64-key tiles. Q/K/V/P staged in smem with conflict-free strides.
// ---------------------------------------------------------------------------
#define FQ 128
#define FK 64
#define QST 132   // bank = (4*row + col) % 32 for frag pattern -> conflict-free
#define KST 132
#define VST 136   // bank = (8*k + d) % 32 -> conflict-free for B frags
#define PST 68    // bank = (4*row + col) % 32

#define FLASH_SMEM_U32 (FQ * QST + FK * KST + FK * VST + FQ * PST)
#define FLASH_SMEM_BYTES (FLASH_SMEM_U32 * 4)

__global__ __launch_bounds__(256)
void flash_tf32_kernel()
{
    extern __shared__ uint32_t fsm[];
    uint32_t* Qs = fsm;                 // [128][132] tf32
    uint32_t* Ks = Qs + FQ * QST;       // [64][132]
    uint32_t* Vs = Ks + FK * KST;       // [64][136]
    uint32_t* Ps = Vs + FK * VST;       // [128][68]

    const int h  = blockIdx.y;
    const int q0 = blockIdx.x * FQ;
    const int tid  = threadIdx.x;
    const int lane = tid & 31;
    const int w    = tid >> 5;          // warp 0..7, owns rows 16w..16w+15
    const int g    = lane >> 2;
    const int q    = lane & 3;
    const int R0   = w * 16;

    // Load Q tile (tf32)
#pragma unroll
    for (int i = 0; i < (FQ * HD) / 256; i++) {
        int idx = i * 256 + tid;
        int r = idx >> 7, d = idx & 127;
        Qs[r * QST + d] = f2tf32(g_q[(size_t)(q0 + r) * DIM + h * HD + d]);
    }

    float m0r = -1e30f, m1r = -1e30f, l0 = 0.f, l1 = 0.f;
    float acc_o[16][4];
#pragma unroll
    for (int nt = 0; nt < 16; nt++)
#pragma unroll
        for (int j = 0; j < 4; j++) acc_o[nt][j] = 0.f;

    const float scale = 0.08838834764831845f;   // 1/sqrt(128)

    for (int kt = 0; kt < S_TOK / FK; kt++) {
        const int kbase = kt * FK;
        __syncthreads();
#pragma unroll
        for (int i = 0; i < (FK * HD) / 256; i++) {
            int idx = i * 256 + tid;
            int r = idx >> 7, d = idx & 127;
            size_t goff = (size_t)(kbase + r) * DIM + h * HD + d;
            Ks[r * KST + d] = f2tf32(g_k[goff]);
            Vs[r * VST + d] = f2tf32(g_v[goff]);
        }
        __syncthreads();

        // ---- scores S = Q K^T  (8 n-tiles of 8 keys) ----
        float sc[8][4];
#pragma unroll
        for (int nt = 0; nt < 8; nt++)
#pragma unroll
            for (int j = 0; j < 4; j++) sc[nt][j] = 0.f;

#pragma unroll
        for (int kk = 0; kk < HD; kk += 8) {
            uint32_t aq[4];
            aq[0] = Qs[(R0 + g)     * QST + kk + q];
            aq[1] = Qs[(R0 + g + 8) * QST + kk + q];
            aq[2] = Qs[(R0 + g)     * QST + kk + q + 4];
            aq[3] = Qs[(R0 + g + 8) * QST + kk + q + 4];
#pragma unroll
            for (int nt = 0; nt < 8; nt++) {
                uint32_t bk2[2];
                bk2[0] = Ks[(nt * 8 + g) * KST + kk + q];
                bk2[1] = Ks[(nt * 8 + g) * KST + kk + q + 4];
                mma_tf32(sc[nt], aq, bk2);
            }
        }

        // ---- online softmax (rows g and g+8 of this warp's 16) ----
        float mx0 = -1e30f, mx1 = -1e30f;
#pragma unroll
        for (int nt = 0; nt < 8; nt++) {
#pragma unroll
            for (int j = 0; j < 4; j++) sc[nt][j] *= scale;
            mx0 = fmaxf(mx0, fmaxf(sc[nt][0], sc[nt][1]));
            mx1 = fmaxf(mx1, fmaxf(sc[nt][2], sc[nt][3]));
        }
        mx0 = fmaxf(mx0, __shfl_xor_sync(0xffffffffu, mx0, 1));
        mx0 = fmaxf(mx0, __shfl_xor_sync(0xffffffffu, mx0, 2));
        mx1 = fmaxf(mx1, __shfl_xor_sync(0xffffffffu, mx1, 1));
        mx1 = fmaxf(mx1, __shfl_xor_sync(0xffffffffu, mx1, 2));

        float mn0 = fmaxf(m0r, mx0);
        float mn1 = fmaxf(m1r, mx1);
        float a0 = __expf(m0r - mn0);
        float a1 = __expf(m1r - mn1);
        m0r = mn0; m1r = mn1;

        float s0 = 0.f, s1 = 0.f;
#pragma unroll
        for (int nt = 0; nt < 8; nt++) {
            float p00 = __expf(sc[nt][0] - mn0);
            float p01 = __expf(sc[nt][1] - mn0);
            float p10 = __expf(sc[nt][2] - mn1);
            float p11 = __expf(sc[nt][3] - mn1);
            s0 += p00 + p01;
            s1 += p10 + p11;
            int c = nt * 8 + 2 * q;
            Ps[(R0 + g)     * PST + c]     = f2tf32(p00);
            Ps[(R0 + g)     * PST + c + 1] = f2tf32(p01);
            Ps[(R0 + g + 8) * PST + c]     = f2tf32(p10);
            Ps[(R0 + g + 8) * PST + c + 1] = f2tf32(p11);
        }
        s0 += __shfl_xor_sync(0xffffffffu, s0, 1);
        s0 += __shfl_xor_sync(0xffffffffu, s0, 2);
        s1 += __shfl_xor_sync(0xffffffffu, s1, 1);
        s1 += __shfl_xor_sync(0xffffffffu, s1, 2);
        l0 = l0 * a0 + s0;
        l1 = l1 * a1 + s1;

#pragma unroll
        for (int nt = 0; nt < 16; nt++) {
            acc_o[nt][0] *= a0; acc_o[nt][1] *= a0;
            acc_o[nt][2] *= a1; acc_o[nt][3] *= a1;
        }
        __syncwarp();   // P written & read within the same warp only

        // ---- O += P V  (16 n-tiles of 8 dims, k = 64 keys) ----
#pragma unroll
        for (int kk = 0; kk < FK; kk += 8) {
            uint32_t ap[4];
            ap[0] = Ps[(R0 + g)     * PST + kk + q];
            ap[1] = Ps[(R0 + g + 8) * PST + kk + q];
            ap[2] = Ps[(R0 + g)     * PST + kk + q + 4];
            ap[3] = Ps[(R0 + g + 8) * PST + kk + q + 4];
#pragma unroll
            for (int nt = 0; nt < 16; nt++) {
                uint32_t bv[2];
                bv[0] = Vs[(kk + q)     * VST + nt * 8 + g];
                bv[1] = Vs[(kk + q + 4) * VST + nt * 8 + g];
                mma_tf32(acc_o[nt], ap, bv);
            }
        }
    }

    // epilogue
    float inv0 = 1.0f / l0;
    float inv1 = 1.0f / l1;
    int row0 = q0 + R0 + g;
#pragma unroll
    for (int nt = 0; nt < 16; nt++) {
        int col = h * HD + nt * 8 + 2 * q;
        float2 v0 = make_float2(acc_o[nt][0] * inv0, acc_o[nt][1] * inv0);
        float2 v1 = make_float2(acc_o[nt][2] * inv1, acc_o[nt][3] * inv1);
        *(float2*)(g_o + (size_t)row0 * DIM + col)       = v0;
        *(float2*)(g_o + (size_t)(row0 + 8) * DIM + col) = v1;
    }
}

// ---------------------------------------------------------------------------
// kernel_launch
// ---------------------------------------------------------------------------
extern "C" void kernel_launch(void* const* d_in, const int* in_sizes, int n_in,
                              void* d_out, int out_size)
{
    const float* x     = (const float*)d_in[0];
    const float* freqs = (const float*)d_in[3];

    int wi = (in_sizes[4] == DIM * DIM) ? 4 : 5;
    const float* Wq = (const float*)d_in[wi + 0];
    const float* bq = (const float*)d_in[wi + 1];
    const float* Wk = (const float*)d_in[wi + 2];
    const float* bk = (const float*)d_in[wi + 3];
    const float* Wv = (const float*)d_in[wi + 4];
    const float* bv = (const float*)d_in[wi + 5];
    const float* Wo = (const float*)d_in[wi + 6];
    const float* bo = (const float*)d_in[wi + 7];
    const float* gq = (const float*)d_in[wi + 8];
    const float* gk = (const float*)d_in[wi + 9];

    float* out = (float*)d_out;

    float *dq, *dk, *dv, *dob;
    cudaGetSymbolAddress((void**)&dq,  g_q);
    cudaGetSymbolAddress((void**)&dk,  g_k);
    cudaGetSymbolAddress((void**)&dv,  g_v);
    cudaGetSymbolAddress((void**)&dob, g_o);

    // 1. RoPE tables
    rope_table_kernel<<<(S_TOK * HD_HALF + 255) / 256, 256>>>(freqs);

    // 2. q/k/v projections (tf32 tensor cores)
    dim3 ggrid(DIM / GBN, S_TOK / GBM);
    gemm_tf32_kernel<<<ggrid, 256>>>(x, Wq, bq, dq, S_TOK, DIM, DIM);
    gemm_tf32_kernel<<<ggrid, 256>>>(x, Wk, bk, dk, S_TOK, DIM, DIM);
    gemm_tf32_kernel<<<ggrid, 256>>>(x, Wv, bv, dv, S_TOK, DIM, DIM);

    // 3. RMSNorm + RoPE on q and k
    norm_rope_kernel<<<S_TOK, 256>>>(gq, gk);

    // 4. flash attention (tf32 tensor cores)
    cudaFuncSetAttribute(flash_tf32_kernel,
                         cudaFuncAttributeMaxDynamicSharedMemorySize,
                         FLASH_SMEM_BYTES);
    dim3 fgrid(S_TOK / FQ, HEADS);
    flash_tf32_kernel<<<fgrid, 256, FLASH_SMEM_BYTES>>>();

    // 5. output projection -> d_out
    gemm_tf32_kernel<<<ggrid, 256>>>(dob, Wo, bo, out, S_TOK, DIM, DIM);

    (void)in_sizes; (void)n_in; (void)out_size;
}

// round 8
// speedup vs baseline: 3.3569x; 1.0028x over previous
#include <cuda_runtime.h>
#include <math.h>
#include <stdint.h>

// Problem constants (fixed by the dataset)
#define S_TOK   4096      // 4*32*32
#define DIM     1536
#define HEADS   12
#define HD      128
#define HD_HALF 64
#define EPS_RMS 1e-6f

// ---------------------------------------------------------------------------
// Scratch (no cudaMalloc allowed): device globals
// ---------------------------------------------------------------------------
__device__ float g_cos[S_TOK * HD_HALF];
__device__ float g_sin[S_TOK * HD_HALF];
__device__ float g_q[S_TOK * DIM];
__device__ float g_k[S_TOK * DIM];
__device__ float g_v[S_TOK * DIM];
__device__ float g_o[S_TOK * DIM];

// ---------------------------------------------------------------------------
// helpers
// ---------------------------------------------------------------------------
__device__ __forceinline__ uint32_t f2tf32(float f) {
    uint32_t r;
    asm("cvt.rna.tf32.f32 %0, %1;\n" : "=r"(r) : "f"(f));
    return r;
}

__device__ __forceinline__ void mma_tf32(float* c, const uint32_t* a, const uint32_t* b) {
    asm volatile(
        "mma.sync.aligned.m16n8k8.row.col.f32.tf32.tf32.f32 "
        "{%0,%1,%2,%3}, {%4,%5,%6,%7}, {%8,%9}, {%0,%1,%2,%3};\n"
        : "+f"(c[0]), "+f"(c[1]), "+f"(c[2]), "+f"(c[3])
        : "r"(a[0]), "r"(a[1]), "r"(a[2]), "r"(a[3]),
          "r"(b[0]), "r"(b[1]));
}

__device__ __forceinline__ void cp_async16(void* smem_dst, const void* gmem_src) {
    uint32_t s = (uint32_t)__cvta_generic_to_shared(smem_dst);
    asm volatile("cp.async.cg.shared.global [%0], [%1], 16;\n" :: "r"(s), "l"(gmem_src));
}
__device__ __forceinline__ void cp_commit() {
    asm volatile("cp.async.commit_group;\n");
}
template<int N>
__device__ __forceinline__ void cp_wait() {
    asm volatile("cp.async.wait_group %0;\n" :: "n"(N));
}

// ---------------------------------------------------------------------------
// RoPE cos/sin tables
// ---------------------------------------------------------------------------
__global__ void rope_table_kernel(const float* __restrict__ freqs)
{
    int idx = blockIdx.x * blockDim.x + threadIdx.x;   // pos*64 + i
    if (idx >= S_TOK * HD_HALF) return;
    int pos = idx >> 6;
    int i   = idx & 63;
    int f = pos >> 10;
    int h = (pos >> 5) & 31;
    int w = pos & 31;
    int row = (i < 22) ? f : ((i < 43) ? h : w);
    float ang = freqs[row * HD_HALF + i];
    g_cos[idx] = cosf(ang);
    g_sin[idx] = sinf(ang);
}

// ---------------------------------------------------------------------------
// TF32 tensor-core GEMM with cp.async 2-stage pipeline
// C[M,N] = A[M,K] @ W[N,K]^T + bias[N]
// 128x128x32 tiles, 8 warps (2x4), warp tile 64x32, m16n8k8
// smem holds fp32; cvt.rna at fragment load.
// ---------------------------------------------------------------------------
#define GBM 128
#define GBN 128
#define GBK 32
#define GST 36     // row stride: bank = (4*row + col) % 32 -> conflict-free frags

#define GEMM_SMEM_FLOATS (2 * (GBM * GST + GBN * GST))
#define GEMM_SMEM_BYTES  (GEMM_SMEM_FLOATS * 4)

__global__ __launch_bounds__(256, 2)
void gemm_tf32_kernel(const float* __restrict__ A,
                      const float* __restrict__ W,
                      const float* __restrict__ bias,
                      float* __restrict__ C,
                      int M, int N, int K)
{
    extern __shared__ float gsm[];
    float* As = gsm;                       // [2][GBM*GST]
    float* Bs = gsm + 2 * GBM * GST;       // [2][GBN*GST]

    const int tid  = threadIdx.x;
    const int lane = tid & 31;
    const int warp = tid >> 5;
    const int wm   = (warp >> 2) * 64;
    const int wn   = (warp & 3) * 32;
    const int g    = lane >> 2;
    const int q    = lane & 3;

    const int m0 = blockIdx.y * GBM;
    const int n0 = blockIdx.x * GBN;

    const int lrow = tid >> 1;           // 0..127
    const int lcol = (tid & 1) * 16;     // 0 or 16

    const float* Ap = A + (size_t)(m0 + lrow) * K + lcol;
    const float* Wp = W + (size_t)(n0 + lrow) * K + lcol;

    float acc[4][4][4];
#pragma unroll
    for (int mi = 0; mi < 4; mi++)
#pragma unroll
        for (int ni = 0; ni < 4; ni++)
#pragma unroll
            for (int j = 0; j < 4; j++) acc[mi][ni][j] = 0.f;

    const int NK = K / GBK;  // 48

    // prologue: stage 0
    {
        float* Ad = As + lrow * GST + lcol;
        float* Bd = Bs + lrow * GST + lcol;
#pragma unroll
        for (int i = 0; i < 4; i++) {
            cp_async16(Ad + 4 * i, Ap + 4 * i);
            cp_async16(Bd + 4 * i, Wp + 4 * i);
        }
        cp_commit();
    }

    for (int kt = 0; kt < NK; kt++) {
        if (kt + 1 < NK) {
            int buf = (kt + 1) & 1;
            int k0  = (kt + 1) * GBK;
            float* Ad = As + buf * GBM * GST + lrow * GST + lcol;
            float* Bd = Bs + buf * GBN * GST + lrow * GST + lcol;
#pragma unroll
            for (int i = 0; i < 4; i++) {
                cp_async16(Ad + 4 * i, Ap + k0 + 4 * i);
                cp_async16(Bd + 4 * i, Wp + k0 + 4 * i);
            }
            cp_commit();
            cp_wait<1>();
        } else {
            cp_wait<0>();
        }
        __syncthreads();

        const float* Ab = As + (kt & 1) * GBM * GST;
        const float* Bb = Bs + (kt & 1) * GBN * GST;

#pragma unroll
        for (int kk = 0; kk < GBK; kk += 8) {
            uint32_t af[4][4], bf[4][2];
#pragma unroll
            for (int mi = 0; mi < 4; mi++) {
                int r = wm + mi * 16;
                af[mi][0] = f2tf32(Ab[(r + g)     * GST + kk + q]);
                af[mi][1] = f2tf32(Ab[(r + g + 8) * GST + kk + q]);
                af[mi][2] = f2tf32(Ab[(r + g)     * GST + kk + q + 4]);
                af[mi][3] = f2tf32(Ab[(r + g + 8) * GST + kk + q + 4]);
            }
#pragma unroll
            for (int ni = 0; ni < 4; ni++) {
                int r = wn + ni * 8 + g;
                bf[ni][0] = f2tf32(Bb[r * GST + kk + q]);
                bf[ni][1] = f2tf32(Bb[r * GST + kk + q + 4]);
            }
#pragma unroll
            for (int mi = 0; mi < 4; mi++)
#pragma unroll
                for (int ni = 0; ni < 4; ni++)
                    mma_tf32(acc[mi][ni], af[mi], bf[ni]);
        }
        __syncthreads();
    }

    // epilogue: bias + store (float2)
#pragma unroll
    for (int mi = 0; mi < 4; mi++) {
        int row0 = m0 + wm + mi * 16 + g;
#pragma unroll
        for (int ni = 0; ni < 4; ni++) {
            int col = n0 + wn + ni * 8 + 2 * q;
            float b0 = bias[col], b1 = bias[col + 1];
            float2 v0 = make_float2(acc[mi][ni][0] + b0, acc[mi][ni][1] + b1);
            float2 v1 = make_float2(acc[mi][ni][2] + b0, acc[mi][ni][3] + b1);
            *(float2*)(C + (size_t)row0 * N + col)       = v0;
            *(float2*)(C + (size_t)(row0 + 8) * N + col) = v1;
        }
    }
}

// ---------------------------------------------------------------------------
// Fused RMSNorm(g) + RoPE for q and k (one block per token)
// ---------------------------------------------------------------------------
__device__ __forceinline__ void norm_rope_row(float* __restrict__ row,
                                              const float* __restrict__ g,
                                              int s, float* red, float* rn_s)
{
    const int tid = threadIdx.x;
    float ss = 0.f;
#pragma unroll
    for (int e = tid; e < DIM; e += 256) {
        float v = row[e];
        ss += v * v;
    }
#pragma unroll
    for (int off = 16; off > 0; off >>= 1)
        ss += __shfl_xor_sync(0xffffffffu, ss, off);
    if ((tid & 31) == 0) red[tid >> 5] = ss;
    __syncthreads();
    if (tid == 0) {
        float t = 0.f;
#pragma unroll
        for (int wgi = 0; wgi < 8; wgi++) t += red[wgi];
        *rn_s = rsqrtf(t * (1.0f / DIM) + EPS_RMS);
    }
    __syncthreads();
    float rn = *rn_s;

    for (int p = tid; p < DIM / 2; p += 256) {
        int i = p & 63;
        float c  = g_cos[s * HD_HALF + i];
        float sn = g_sin[s * HD_HALF + i];
        float xe = row[2 * p]     * rn * g[2 * p];
        float xo = row[2 * p + 1] * rn * g[2 * p + 1];
        row[2 * p]     = xe * c - xo * sn;
        row[2 * p + 1] = xe * sn + xo * c;
    }
    __syncthreads();
}

__global__ __launch_bounds__(256)
void norm_rope_kernel(const float* __restrict__ gq, const float* __restrict__ gk)
{
    __shared__ float red[8];
    __shared__ float rn_s;
    int s = blockIdx.x;
    norm_rope_row(g_q + (size_t)s * DIM, gq, s, red, &rn_s);
    norm_rope_row(g_k + (size_t)s * DIM, gk, s, red, &rn_s);
}

// ---------------------------------------------------------------------------
// Flash attention, tf32 tensor cores, cp.async pipelined K (2-stage) + V.
// 256 threads (8 warps); warp w owns query rows 16w..16w+15; 64-key tiles.
// Q in smem as tf32 (converted once); K/V in smem as fp32 (cvt at frag load);
// P staged in smem as tf32.
// ---------------------------------------------------------------------------
#define FQ 128
#define FK 64
#define QST 132   // bank = (4*row + col) % 32 -> conflict-free A frags
#define KST 132
#define VST 136   // bank = (8*k + d) % 32 -> conflict-free B frags
#define PST 68

#define FL_K (FQ * QST)
#define FL_V (FL_K + 2 * FK * KST)
#define FL_P (FL_V + FK * VST)
#define FLASH_SMEM_U32 (FL_P + FQ * PST)
#define FLASH_SMEM_BYTES (FLASH_SMEM_U32 * 4)   // 204800 B

__global__ __launch_bounds__(256, 1)
void flash_tf32_kernel()
{
    extern __shared__ uint32_t fsm[];
    uint32_t* Qs = fsm;                        // [128][132] tf32
    float*    Ks = (float*)(fsm + FL_K);       // [2][64][132] fp32
    float*    Vs = (float*)(fsm + FL_V);       // [64][136]    fp32
    uint32_t* Ps = fsm + FL_P;                 // [128][68]    tf32

    const int h  = blockIdx.y;
    const int q0 = blockIdx.x * FQ;
    const int tid  = threadIdx.x;
    const int lane = tid & 31;
    const int w    = tid >> 5;
    const int g    = lane >> 2;
    const int q    = lane & 3;
    const int R0   = w * 16;
    const size_t hoff = (size_t)h * HD;

    // ---- load Q tile once, convert to tf32 (vectorized) ----
#pragma unroll
    for (int i = 0; i < 16; i++) {
        int idx4 = i * 256 + tid;            // 4096 float4
        int r = idx4 >> 5, c = (idx4 & 31) * 4;
        float4 v = *(const float4*)(g_q + (size_t)(q0 + r) * DIM + hoff + c);
        Qs[r * QST + c + 0] = f2tf32(v.x);
        Qs[r * QST + c + 1] = f2tf32(v.y);
        Qs[r * QST + c + 2] = f2tf32(v.z);
        Qs[r * QST + c + 3] = f2tf32(v.w);
    }

    // ---- prologue: stage K0 (buf 0) then V0 ----
    {
#pragma unroll
        for (int i = 0; i < 8; i++) {
            int idx4 = i * 256 + tid;        // 2048 float4
            int r = idx4 >> 5, c = (idx4 & 31) * 4;
            cp_async16(Ks + r * KST + c, g_k + (size_t)r * DIM + hoff + c);
        }
        cp_commit();
#pragma unroll
        for (int i = 0; i < 8; i++) {
            int idx4 = i * 256 + tid;
            int r = idx4 >> 5, c = (idx4 & 31) * 4;
            cp_async16(Vs + r * VST + c, g_v + (size_t)r * DIM + hoff + c);
        }
        cp_commit();
    }

    float m0r = -1e30f, m1r = -1e30f, l0 = 0.f, l1 = 0.f;
    float acc_o[16][4];
#pragma unroll
    for (int nt = 0; nt < 16; nt++)
#pragma unroll
        for (int j = 0; j < 4; j++) acc_o[nt][j] = 0.f;

    const float scale = 0.08838834764831845f;   // 1/sqrt(128)
    const int NT = S_TOK / FK;                  // 64

    for (int kt = 0; kt < NT; kt++) {
        // stage K(kt+1) into the other buffer, then wait for K(kt)/V(kt)
        if (kt + 1 < NT) {
            float* Kd = Ks + ((kt + 1) & 1) * FK * KST;
            const size_t kb = (size_t)(kt + 1) * FK;
#pragma unroll
            for (int i = 0; i < 8; i++) {
                int idx4 = i * 256 + tid;
                int r = idx4 >> 5, c = (idx4 & 31) * 4;
                cp_async16(Kd + r * KST + c, g_k + (kb + r) * DIM + hoff + c);
            }
            cp_commit();
            cp_wait<1>();
        } else {
            cp_wait<0>();
        }
        __syncthreads();

        const float* Kb = Ks + (kt & 1) * FK * KST;

        // ---- scores S = Q K^T ----
        float sc[8][4];
#pragma unroll
        for (int nt = 0; nt < 8; nt++)
#pragma unroll
            for (int j = 0; j < 4; j++) sc[nt][j] = 0.f;

#pragma unroll
        for (int kk = 0; kk < HD; kk += 8) {
            uint32_t aq[4];
            aq[0] = Qs[(R0 + g)     * QST + kk + q];
            aq[1] = Qs[(R0 + g + 8) * QST + kk + q];
            aq[2] = Qs[(R0 + g)     * QST + kk + q + 4];
            aq[3] = Qs[(R0 + g + 8) * QST + kk + q + 4];
#pragma unroll
            for (int nt = 0; nt < 8; nt++) {
                uint32_t bk2[2];
                bk2[0] = f2tf32(Kb[(nt * 8 + g) * KST + kk + q]);
                bk2[1] = f2tf32(Kb[(nt * 8 + g) * KST + kk + q + 4]);
                mma_tf32(sc[nt], aq, bk2);
            }
        }

        // ---- online softmax ----
        float mx0 = -1e30f, mx1 = -1e30f;
#pragma unroll
        for (int nt = 0; nt < 8; nt++) {
#pragma unroll
            for (int j = 0; j < 4; j++) sc[nt][j] *= scale;
            mx0 = fmaxf(mx0, fmaxf(sc[nt][0], sc[nt][1]));
            mx1 = fmaxf(mx1, fmaxf(sc[nt][2], sc[nt][3]));
        }
        mx0 = fmaxf(mx0, __shfl_xor_sync(0xffffffffu, mx0, 1));
        mx0 = fmaxf(mx0, __shfl_xor_sync(0xffffffffu, mx0, 2));
        mx1 = fmaxf(mx1, __shfl_xor_sync(0xffffffffu, mx1, 1));
        mx1 = fmaxf(mx1, __shfl_xor_sync(0xffffffffu, mx1, 2));

        float mn0 = fmaxf(m0r, mx0);
        float mn1 = fmaxf(m1r, mx1);
        float a0 = __expf(m0r - mn0);
        float a1 = __expf(m1r - mn1);
        m0r = mn0; m1r = mn1;

        float s0 = 0.f, s1 = 0.f;
#pragma unroll
        for (int nt = 0; nt < 8; nt++) {
            float p00 = __expf(sc[nt][0] - mn0);
            float p01 = __expf(sc[nt][1] - mn0);
            float p10 = __expf(sc[nt][2] - mn1);
            float p11 = __expf(sc[nt][3] - mn1);
            s0 += p00 + p01;
            s1 += p10 + p11;
            int c = nt * 8 + 2 * q;
            Ps[(R0 + g)     * PST + c]     = f2tf32(p00);
            Ps[(R0 + g)     * PST + c + 1] = f2tf32(p01);
            Ps[(R0 + g + 8) * PST + c]     = f2tf32(p10);
            Ps[(R0 + g + 8) * PST + c + 1] = f2tf32(p11);
        }
        s0 += __shfl_xor_sync(0xffffffffu, s0, 1);
        s0 += __shfl_xor_sync(0xffffffffu, s0, 2);
        s1 += __shfl_xor_sync(0xffffffffu, s1, 1);
        s1 += __shfl_xor_sync(0xffffffffu, s1, 2);
        l0 = l0 * a0 + s0;
        l1 = l1 * a1 + s1;

#pragma unroll
        for (int nt = 0; nt < 16; nt++) {
            acc_o[nt][0] *= a0; acc_o[nt][1] *= a0;
            acc_o[nt][2] *= a1; acc_o[nt][3] *= a1;
        }
        __syncwarp();   // P written & read within the same warp only

        // ---- O += P V ----
#pragma unroll
        for (int kk = 0; kk < FK; kk += 8) {
            uint32_t ap[4];
            ap[0] = Ps[(R0 + g)     * PST + kk + q];
            ap[1] = Ps[(R0 + g + 8) * PST + kk + q];
            ap[2] = Ps[(R0 + g)     * PST + kk + q + 4];
            ap[3] = Ps[(R0 + g + 8) * PST + kk + q + 4];
#pragma unroll
            for (int nt = 0; nt < 16; nt++) {
                uint32_t bv[2];
                bv[0] = f2tf32(Vs[(kk + q)     * VST + nt * 8 + g]);
                bv[1] = f2tf32(Vs[(kk + q + 4) * VST + nt * 8 + g]);
                mma_tf32(acc_o[nt], ap, bv);
            }
        }
        __syncthreads();   // all warps done reading Vs

        // stage V(kt+1) (single buffer; covered by next score phase)
        if (kt + 1 < NT) {
            const size_t kb = (size_t)(kt + 1) * FK;
#pragma unroll
            for (int i = 0; i < 8; i++) {
                int idx4 = i * 256 + tid;
                int r = idx4 >> 5, c = (idx4 & 31) * 4;
                cp_async16(Vs + r * VST + c, g_v + (kb + r) * DIM + hoff + c);
            }
            cp_commit();
        }
    }

    // epilogue
    float inv0 = 1.0f / l0;
    float inv1 = 1.0f / l1;
    int row0 = q0 + R0 + g;
#pragma unroll
    for (int nt = 0; nt < 16; nt++) {
        int col = h * HD + nt * 8 + 2 * q;
        float2 v0 = make_float2(acc_o[nt][0] * inv0, acc_o[nt][1] * inv0);
        float2 v1 = make_float2(acc_o[nt][2] * inv1, acc_o[nt][3] * inv1);
        *(float2*)(g_o + (size_t)row0 * DIM + col)       = v0;
        *(float2*)(g_o + (size_t)(row0 + 8) * DIM + col) = v1;
    }
}

// ---------------------------------------------------------------------------
// kernel_launch
// ---------------------------------------------------------------------------
extern "C" void kernel_launch(void* const* d_in, const int* in_sizes, int n_in,
                              void* d_out, int out_size)
{
    const float* x     = (const float*)d_in[0];
    const float* freqs = (const float*)d_in[3];

    int wi = (in_sizes[4] == DIM * DIM) ? 4 : 5;
    const float* Wq = (const float*)d_in[wi + 0];
    const float* bq = (const float*)d_in[wi + 1];
    const float* Wk = (const float*)d_in[wi + 2];
    const float* bk = (const float*)d_in[wi + 3];
    const float* Wv = (const float*)d_in[wi + 4];
    const float* bv = (const float*)d_in[wi + 5];
    const float* Wo = (const float*)d_in[wi + 6];
    const float* bo = (const float*)d_in[wi + 7];
    const float* gq = (const float*)d_in[wi + 8];
    const float* gk = (const float*)d_in[wi + 9];

    float* out = (float*)d_out;

    float *dq, *dk, *dv, *dob;
    cudaGetSymbolAddress((void**)&dq,  g_q);
    cudaGetSymbolAddress((void**)&dk,  g_k);
    cudaGetSymbolAddress((void**)&dv,  g_v);
    cudaGetSymbolAddress((void**)&dob, g_o);

    cudaFuncSetAttribute(gemm_tf32_kernel,
                         cudaFuncAttributeMaxDynamicSharedMemorySize,
                         GEMM_SMEM_BYTES);
    cudaFuncSetAttribute(flash_tf32_kernel,
                         cudaFuncAttributeMaxDynamicSharedMemorySize,
                         FLASH_SMEM_BYTES);

    // 1. RoPE tables
    rope_table_kernel<<<(S_TOK * HD_HALF + 255) / 256, 256>>>(freqs);

    // 2. q/k/v projections (tf32 tensor cores, cp.async pipelined)
    dim3 ggrid(DIM / GBN, S_TOK / GBM);
    gemm_tf32_kernel<<<ggrid, 256, GEMM_SMEM_BYTES>>>(x, Wq, bq, dq, S_TOK, DIM, DIM);
    gemm_tf32_kernel<<<ggrid, 256, GEMM_SMEM_BYTES>>>(x, Wk, bk, dk, S_TOK, DIM, DIM);
    gemm_tf32_kernel<<<ggrid, 256, GEMM_SMEM_BYTES>>>(x, Wv, bv, dv, S_TOK, DIM, DIM);

    // 3. RMSNorm + RoPE on q and k
    norm_rope_kernel<<<S_TOK, 256>>>(gq, gk);

    // 4. flash attention
    dim3 fgrid(S_TOK / FQ, HEADS);
    flash_tf32_kernel<<<fgrid, 256, FLASH_SMEM_BYTES>>>();

    // 5. output projection -> d_out
    gemm_tf32_kernel<<<ggrid, 256, GEMM_SMEM_BYTES>>>(dob, Wo, bo, out, S_TOK, DIM, DIM);

    (void)in_sizes; (void)n_in; (void)out_size;
}

// round 10
// speedup vs baseline: 6.5134x; 1.9403x over previous
#include <cuda_runtime.h>
#include <cuda_fp16.h>
#include <math.h>
#include <stdint.h>

// Problem constants (fixed by the dataset)
#define S_TOK   4096      // 4*32*32
#define DIM     1536
#define HEADS   12
#define HD      128
#define HD_HALF 64
#define EPS_RMS 1e-6f

// ---------------------------------------------------------------------------
// Scratch (no cudaMalloc allowed): device globals
// ---------------------------------------------------------------------------
__device__ float  g_cos[S_TOK * HD_HALF];
__device__ float  g_sin[S_TOK * HD_HALF];
__device__ float  g_q[S_TOK * DIM];        // fp32 q (pre-norm)
__device__ float  g_k[S_TOK * DIM];        // fp32 k (pre-norm)
__device__ __half g_xh[S_TOK * DIM];       // half x
__device__ __half g_qh[S_TOK * DIM];       // half q (post norm+rope)
__device__ __half g_kh[S_TOK * DIM];
__device__ __half g_vh[S_TOK * DIM];
__device__ __half g_oh[S_TOK * DIM];       // half attention output
__device__ __half g_wh[4 * DIM * DIM];     // half Wq,Wk,Wv,Wo

// ---------------------------------------------------------------------------
// helpers
// ---------------------------------------------------------------------------
__device__ __forceinline__ uint32_t smem_u32(const void* p) {
    return (uint32_t)__cvta_generic_to_shared(p);
}

__device__ __forceinline__ void ldsm_x4(uint32_t* r, uint32_t addr) {
    asm volatile("ldmatrix.sync.aligned.m8n8.x4.shared.b16 {%0,%1,%2,%3}, [%4];\n"
        : "=r"(r[0]), "=r"(r[1]), "=r"(r[2]), "=r"(r[3]) : "r"(addr));
}
__device__ __forceinline__ void ldsm_x4_trans(uint32_t* r, uint32_t addr) {
    asm volatile("ldmatrix.sync.aligned.m8n8.x4.trans.shared.b16 {%0,%1,%2,%3}, [%4];\n"
        : "=r"(r[0]), "=r"(r[1]), "=r"(r[2]), "=r"(r[3]) : "r"(addr));
}

__device__ __forceinline__ void mma_f16(float* c, const uint32_t* a, const uint32_t* b) {
    asm volatile(
        "mma.sync.aligned.m16n8k16.row.col.f32.f16.f16.f32 "
        "{%0,%1,%2,%3}, {%4,%5,%6,%7}, {%8,%9}, {%0,%1,%2,%3};\n"
        : "+f"(c[0]), "+f"(c[1]), "+f"(c[2]), "+f"(c[3])
        : "r"(a[0]), "r"(a[1]), "r"(a[2]), "r"(a[3]),
          "r"(b[0]), "r"(b[1]));
}

__device__ __forceinline__ void cp_async16(void* smem_dst, const void* gmem_src) {
    uint32_t s = (uint32_t)__cvta_generic_to_shared(smem_dst);
    asm volatile("cp.async.cg.shared.global [%0], [%1], 16;\n" :: "r"(s), "l"(gmem_src));
}
__device__ __forceinline__ void cp_commit() {
    asm volatile("cp.async.commit_group;\n");
}
template<int N>
__device__ __forceinline__ void cp_wait() {
    asm volatile("cp.async.wait_group %0;\n" :: "n"(N));
}

// ---------------------------------------------------------------------------
// fp32 -> fp16 conversion (vectorized)
// ---------------------------------------------------------------------------
__global__ void cvt_f16_kernel(const float* __restrict__ src,
                               __half* __restrict__ dst, int n4)
{
    int i = blockIdx.x * blockDim.x + threadIdx.x;
    if (i >= n4) return;
    float4 v = ((const float4*)src)[i];
    __half2* d = (__half2*)(dst + 4 * i);
    d[0] = __floats2half2_rn(v.x, v.y);
    d[1] = __floats2half2_rn(v.z, v.w);
}

// ---------------------------------------------------------------------------
// RoPE cos/sin tables
// ---------------------------------------------------------------------------
__global__ void rope_table_kernel(const float* __restrict__ freqs)
{
    int idx = blockIdx.x * blockDim.x + threadIdx.x;   // pos*64 + i
    if (idx >= S_TOK * HD_HALF) return;
    int pos = idx >> 6;
    int i   = idx & 63;
    int f = pos >> 10;
    int h = (pos >> 5) & 31;
    int w = pos & 31;
    int row = (i < 22) ? f : ((i < 43) ? h : w);
    float ang = freqs[row * HD_HALF + i];
    g_cos[idx] = cosf(ang);
    g_sin[idx] = sinf(ang);
}

// ---------------------------------------------------------------------------
// FP16 tensor-core GEMM: C[M,N] = A[M,K] @ W[N,K]^T + bias[N]
// A,W half; accum fp32. 128x128x64 tiles, 8 warps (2x4), warp 64x32,
// m16n8k16 mma + ldmatrix, cp.async 2-stage pipeline.
// ---------------------------------------------------------------------------
#define GBM 128
#define GBN 128
#define GBK 64
#define HST 72     // half stride: 144B rows

#define GEMM_SMEM_BYTES (2 * (GBM * HST + GBN * HST) * 2)   // 73728

__global__ __launch_bounds__(256, 2)
void gemm_f16_kernel(const __half* __restrict__ A,
                     const __half* __restrict__ W,
                     const float* __restrict__ bias,
                     float* __restrict__ Cf,
                     __half* __restrict__ Ch,
                     int out_half, int M, int N, int K)
{
    extern __shared__ __half hsm[];
    __half* As = hsm;                        // [2][GBM*HST]
    __half* Bs = hsm + 2 * GBM * HST;        // [2][GBN*HST]

    const int tid  = threadIdx.x;
    const int lane = tid & 31;
    const int warp = tid >> 5;
    const int wm   = (warp >> 2) * 64;
    const int wn   = (warp & 3) * 32;
    const int g    = lane >> 2;
    const int q    = lane & 3;

    const int m0 = blockIdx.y * GBM;
    const int n0 = blockIdx.x * GBN;

    // staging: 128 rows x 64 cols: 2 threads/row, 32 cols each (4x16B)
    const int srow = tid >> 1;
    const int scol = (tid & 1) * 32;
    const __half* Ap = A + (size_t)(m0 + srow) * K + scol;
    const __half* Wp = W + (size_t)(n0 + srow) * K + scol;

    float acc[4][4][4];
#pragma unroll
    for (int mi = 0; mi < 4; mi++)
#pragma unroll
        for (int ni = 0; ni < 4; ni++)
#pragma unroll
            for (int j = 0; j < 4; j++) acc[mi][ni][j] = 0.f;

    const int NK = K / GBK;   // 24

    // prologue: stage 0
    {
        __half* Ad = As + srow * HST + scol;
        __half* Bd = Bs + srow * HST + scol;
#pragma unroll
        for (int j = 0; j < 4; j++) {
            cp_async16(Ad + 8 * j, Ap + 8 * j);
            cp_async16(Bd + 8 * j, Wp + 8 * j);
        }
        cp_commit();
    }

    // ldmatrix lane-address components
    const int a_row = lane & 15;
    const int a_col = (lane >> 4) * 8;
    const int b_row = ((lane >> 4) * 8) + (lane & 7);
    const int b_col = ((lane >> 3) & 1) * 8;

    for (int kt = 0; kt < NK; kt++) {
        if (kt + 1 < NK) {
            int buf = (kt + 1) & 1;
            int k0  = (kt + 1) * GBK;
            __half* Ad = As + buf * GBM * HST + srow * HST + scol;
            __half* Bd = Bs + buf * GBN * HST + srow * HST + scol;
#pragma unroll
            for (int j = 0; j < 4; j++) {
                cp_async16(Ad + 8 * j, Ap + k0 + 8 * j);
                cp_async16(Bd + 8 * j, Wp + k0 + 8 * j);
            }
            cp_commit();
            cp_wait<1>();
        } else {
            cp_wait<0>();
        }
        __syncthreads();

        const uint32_t sA = smem_u32(As + (kt & 1) * GBM * HST);
        const uint32_t sB = smem_u32(Bs + (kt & 1) * GBN * HST);

#pragma unroll
        for (int kk = 0; kk < GBK; kk += 16) {
            uint32_t af[4][4], bf[4][2];
#pragma unroll
            for (int mi = 0; mi < 4; mi++)
                ldsm_x4(af[mi], sA + ((wm + 16 * mi + a_row) * HST + kk + a_col) * 2);
#pragma unroll
            for (int p = 0; p < 2; p++) {
                uint32_t r[4];
                ldsm_x4(r, sB + ((wn + 16 * p + b_row) * HST + kk + b_col) * 2);
                bf[2 * p][0] = r[0]; bf[2 * p][1] = r[1];
                bf[2 * p + 1][0] = r[2]; bf[2 * p + 1][1] = r[3];
            }
#pragma unroll
            for (int mi = 0; mi < 4; mi++)
#pragma unroll
                for (int ni = 0; ni < 4; ni++)
                    mma_f16(acc[mi][ni], af[mi], bf[ni]);
        }
        __syncthreads();
    }

    // epilogue
#pragma unroll
    for (int mi = 0; mi < 4; mi++) {
        int row0 = m0 + wm + mi * 16 + g;
#pragma unroll
        for (int ni = 0; ni < 4; ni++) {
            int col = n0 + wn + ni * 8 + 2 * q;
            float b0 = bias[col], b1 = bias[col + 1];
            float o00 = acc[mi][ni][0] + b0, o01 = acc[mi][ni][1] + b1;
            float o10 = acc[mi][ni][2] + b0, o11 = acc[mi][ni][3] + b1;
            if (out_half) {
                *(__half2*)(Ch + (size_t)row0 * N + col)       = __floats2half2_rn(o00, o01);
                *(__half2*)(Ch + (size_t)(row0 + 8) * N + col) = __floats2half2_rn(o10, o11);
            } else {
                *(float2*)(Cf + (size_t)row0 * N + col)       = make_float2(o00, o01);
                *(float2*)(Cf + (size_t)(row0 + 8) * N + col) = make_float2(o10, o11);
            }
        }
    }
}

// ---------------------------------------------------------------------------
// Fused RMSNorm(g) + RoPE: fp32 in, fp16 out
// ---------------------------------------------------------------------------
__device__ __forceinline__ void norm_rope_row(const float* __restrict__ row,
                                              __half* __restrict__ outh,
                                              const float* __restrict__ g,
                                              int s, float* red, float* rn_s)
{
    const int tid = threadIdx.x;
    float ss = 0.f;
#pragma unroll
    for (int e = tid; e < DIM; e += 256) {
        float v = row[e];
        ss += v * v;
    }
#pragma unroll
    for (int off = 16; off > 0; off >>= 1)
        ss += __shfl_xor_sync(0xffffffffu, ss, off);
    if ((tid & 31) == 0) red[tid >> 5] = ss;
    __syncthreads();
    if (tid == 0) {
        float t = 0.f;
#pragma unroll
        for (int wgi = 0; wgi < 8; wgi++) t += red[wgi];
        *rn_s = rsqrtf(t * (1.0f / DIM) + EPS_RMS);
    }
    __syncthreads();
    float rn = *rn_s;

    for (int p = tid; p < DIM / 2; p += 256) {
        int i = p & 63;
        float c  = g_cos[s * HD_HALF + i];
        float sn = g_sin[s * HD_HALF + i];
        float xe = row[2 * p]     * rn * g[2 * p];
        float xo = row[2 * p + 1] * rn * g[2 * p + 1];
        *(__half2*)(outh + 2 * p) =
            __floats2half2_rn(xe * c - xo * sn, xe * sn + xo * c);
    }
    __syncthreads();
}

__global__ __launch_bounds__(256)
void norm_rope_kernel(const float* __restrict__ gq, const float* __restrict__ gk)
{
    __shared__ float red[8];
    __shared__ float rn_s;
    int s = blockIdx.x;
    norm_rope_row(g_q + (size_t)s * DIM, g_qh + (size_t)s * DIM, gq, s, red, &rn_s);
    norm_rope_row(g_k + (size_t)s * DIM, g_kh + (size_t)s * DIM, gk, s, red, &rn_s);
}

// ---------------------------------------------------------------------------
// Flash attention, fp16 mma m16n8k16 + ldmatrix, fp32 accumulators.
// 256 threads (8 warps); warp w owns query rows 16w..16w+15; 64-key tiles.
// K double-buffered (cp.async), V single-buffered, P through smem (half).
// ---------------------------------------------------------------------------
#define FQ 128
#define FK 64
#define FSTR 136   // Q/K/V half stride (272B rows)
#define PSTR 72    // P half stride (144B rows)

#define FL_Q 0
#define FL_K (FQ * FSTR)
#define FL_V (FL_K + 2 * FK * FSTR)
#define FL_P (FL_V + FK * FSTR)
#define FLASH_SMEM_HALVES (FL_P + FQ * PSTR)
#define FLASH_SMEM_BYTES  (FLASH_SMEM_HALVES * 2)    // 105472

__global__ __launch_bounds__(256)
void flash_f16_kernel()
{
    extern __shared__ __half fsm[];
    __half* Qs = fsm + FL_Q;       // [128][136]
    __half* Ks = fsm + FL_K;       // [2][64][136]
    __half* Vs = fsm + FL_V;       // [64][136]
    __half* Ps = fsm + FL_P;       // [128][72]

    const int h  = blockIdx.y;
    const int q0 = blockIdx.x * FQ;
    const int tid  = threadIdx.x;
    const int lane = tid & 31;
    const int w    = tid >> 5;
    const int g    = lane >> 2;
    const int q    = lane & 3;
    const int R0   = w * 16;
    const size_t hoff = (size_t)h * HD;

    // staging coords:
    //   Q: 128 rows, 2 threads/row covering 64 cols each (8 x 16B)
    //   K/V: 64 rows, 4 threads/row covering 32 cols each (4 x 16B)
    const int qrow = tid >> 1;
    const int qcol = (tid & 1) * 64;
    const int krow = tid >> 2;           // 0..63
    const int kcol = (tid & 3) * 32;     // 0,32,64,96

    // ---- prologue: stage Q + K0 (group 1), V0 (group 2) ----
    {
        __half* Qd = Qs + qrow * FSTR + qcol;
        const __half* Qg = g_qh + (size_t)(q0 + qrow) * DIM + hoff + qcol;
#pragma unroll
        for (int j = 0; j < 8; j++) cp_async16(Qd + 8 * j, Qg + 8 * j);

        __half* Kd = Ks + krow * FSTR + kcol;
        const __half* Kg = g_kh + (size_t)krow * DIM + hoff + kcol;
#pragma unroll
        for (int j = 0; j < 4; j++) cp_async16(Kd + 8 * j, Kg + 8 * j);
        cp_commit();

        __half* Vd = Vs + krow * FSTR + kcol;
        const __half* Vg = g_vh + (size_t)krow * DIM + hoff + kcol;
#pragma unroll
        for (int j = 0; j < 4; j++) cp_async16(Vd + 8 * j, Vg + 8 * j);
        cp_commit();
    }

    float m0r = -1e30f, m1r = -1e30f, l0 = 0.f, l1 = 0.f;
    float acc_o[16][4];
#pragma unroll
    for (int nt = 0; nt < 16; nt++)
#pragma unroll
        for (int j = 0; j < 4; j++) acc_o[nt][j] = 0.f;

    const float scale = 0.08838834764831845f;   // 1/sqrt(128)
    const int NT = S_TOK / FK;                  // 64

    const uint32_t sQ = smem_u32(Qs);
    const uint32_t sV = smem_u32(Vs);
    const uint32_t sP = smem_u32(Ps);

    // ldmatrix lane components
    const int a_row = lane & 15;
    const int a_col = (lane >> 4) * 8;
    const int b_row = ((lane >> 4) * 8) + (lane & 7);
    const int b_col = ((lane >> 3) & 1) * 8;

    for (int kt = 0; kt < NT; kt++) {
        if (kt + 1 < NT) {
            __half* Kd = Ks + ((kt + 1) & 1) * FK * FSTR + krow * FSTR + kcol;
            const __half* Kg = g_kh + (size_t)((kt + 1) * FK + krow) * DIM + hoff + kcol;
#pragma unroll
            for (int j = 0; j < 4; j++) cp_async16(Kd + 8 * j, Kg + 8 * j);
            cp_commit();
            cp_wait<1>();
        } else {
            cp_wait<0>();
        }
        __syncthreads();

        const uint32_t sK = smem_u32(Ks + (kt & 1) * FK * FSTR);

        // ---- scores S = Q K^T ----
        float sc[8][4];
#pragma unroll
        for (int nt = 0; nt < 8; nt++)
#pragma unroll
            for (int j = 0; j < 4; j++) sc[nt][j] = 0.f;

#pragma unroll
        for (int kk = 0; kk < HD; kk += 16) {
            uint32_t aq[4];
            ldsm_x4(aq, sQ + ((R0 + a_row) * FSTR + kk + a_col) * 2);
#pragma unroll
            for (int p = 0; p < 4; p++) {
                uint32_t r[4];
                ldsm_x4(r, sK + ((16 * p + b_row) * FSTR + kk + b_col) * 2);
                mma_f16(sc[2 * p],     aq, r);
                mma_f16(sc[2 * p + 1], aq, r + 2);
            }
        }

        // ---- online softmax ----
        float mx0 = -1e30f, mx1 = -1e30f;
#pragma unroll
        for (int nt = 0; nt < 8; nt++) {
#pragma unroll
            for (int j = 0; j < 4; j++) sc[nt][j] *= scale;
            mx0 = fmaxf(mx0, fmaxf(sc[nt][0], sc[nt][1]));
            mx1 = fmaxf(mx1, fmaxf(sc[nt][2], sc[nt][3]));
        }
        mx0 = fmaxf(mx0, __shfl_xor_sync(0xffffffffu, mx0, 1));
        mx0 = fmaxf(mx0, __shfl_xor_sync(0xffffffffu, mx0, 2));
        mx1 = fmaxf(mx1, __shfl_xor_sync(0xffffffffu, mx1, 1));
        mx1 = fmaxf(mx1, __shfl_xor_sync(0xffffffffu, mx1, 2));

        float mn0 = fmaxf(m0r, mx0);
        float mn1 = fmaxf(m1r, mx1);
        float a0 = __expf(m0r - mn0);
        float a1 = __expf(m1r - mn1);
        m0r = mn0; m1r = mn1;

        float s0 = 0.f, s1 = 0.f;
#pragma unroll
        for (int nt = 0; nt < 8; nt++) {
            float p00 = __expf(sc[nt][0] - mn0);
            float p01 = __expf(sc[nt][1] - mn0);
            float p10 = __expf(sc[nt][2] - mn1);
            float p11 = __expf(sc[nt][3] - mn1);
            s0 += p00 + p01;
            s1 += p10 + p11;
            int c = nt * 8 + 2 * q;
            *(__half2*)(Ps + (R0 + g)     * PSTR + c) = __floats2half2_rn(p00, p01);
            *(__half2*)(Ps + (R0 + g + 8) * PSTR + c) = __floats2half2_rn(p10, p11);
        }
        s0 += __shfl_xor_sync(0xffffffffu, s0, 1);
        s0 += __shfl_xor_sync(0xffffffffu, s0, 2);
        s1 += __shfl_xor_sync(0xffffffffu, s1, 1);
        s1 += __shfl_xor_sync(0xffffffffu, s1, 2);
        l0 = l0 * a0 + s0;
        l1 = l1 * a1 + s1;

#pragma unroll
        for (int nt = 0; nt < 16; nt++) {
            acc_o[nt][0] *= a0; acc_o[nt][1] *= a0;
            acc_o[nt][2] *= a1; acc_o[nt][3] *= a1;
        }
        __syncwarp();   // P written & read within the same warp only

        // ---- O += P V ----
#pragma unroll
        for (int kk = 0; kk < FK; kk += 16) {
            uint32_t ap[4];
            ldsm_x4(ap, sP + ((R0 + a_row) * PSTR + kk + a_col) * 2);
#pragma unroll
            for (int p = 0; p < 8; p++) {
                uint32_t r[4];
                // V trans: rows = keys, cols = dims
                ldsm_x4_trans(r, sV + ((kk + b_col + (lane & 7)) * FSTR
                                        + 16 * p + (lane >> 4) * 8) * 2);
                mma_f16(acc_o[2 * p],     ap, r);
                mma_f16(acc_o[2 * p + 1], ap, r + 2);
            }
        }
        __syncthreads();   // all warps done reading Vs

        // stage V(kt+1): hidden under next score phase
        if (kt + 1 < NT) {
            __half* Vd = Vs + krow * FSTR + kcol;
            const __half* Vg = g_vh + (size_t)((kt + 1) * FK + krow) * DIM + hoff + kcol;
#pragma unroll
            for (int j = 0; j < 4; j++) cp_async16(Vd + 8 * j, Vg + 8 * j);
            cp_commit();
        }
    }

    // epilogue -> half output for O-projection
    float inv0 = 1.0f / l0;
    float inv1 = 1.0f / l1;
    int row0 = q0 + R0 + g;
#pragma unroll
    for (int nt = 0; nt < 16; nt++) {
        int col = (int)hoff + nt * 8 + 2 * q;
        *(__half2*)(g_oh + (size_t)row0 * DIM + col) =
            __floats2half2_rn(acc_o[nt][0] * inv0, acc_o[nt][1] * inv0);
        *(__half2*)(g_oh + (size_t)(row0 + 8) * DIM + col) =
            __floats2half2_rn(acc_o[nt][2] * inv1, acc_o[nt][3] * inv1);
    }
}

// ---------------------------------------------------------------------------
// kernel_launch
// ---------------------------------------------------------------------------
extern "C" void kernel_launch(void* const* d_in, const int* in_sizes, int n_in,
                              void* d_out, int out_size)
{
    const float* x     = (const float*)d_in[0];
    const float* freqs = (const float*)d_in[3];

    int wi = (in_sizes[4] == DIM * DIM) ? 4 : 5;
    const float* Wq = (const float*)d_in[wi + 0];
    const float* bq = (const float*)d_in[wi + 1];
    const float* Wk = (const float*)d_in[wi + 2];
    const float* bk = (const float*)d_in[wi + 3];
    const float* Wv = (const float*)d_in[wi + 4];
    const float* bv = (const float*)d_in[wi + 5];
    const float* Wo = (const float*)d_in[wi + 6];
    const float* bo = (const float*)d_in[wi + 7];
    const float* gq = (const float*)d_in[wi + 8];
    const float* gk = (const float*)d_in[wi + 9];

    float* out = (float*)d_out;

    float *dq, *dk;
    __half *dxh, *dqh, *dkh, *dvh, *doh, *dwh;
    cudaGetSymbolAddress((void**)&dq,  g_q);
    cudaGetSymbolAddress((void**)&dk,  g_k);
    cudaGetSymbolAddress((void**)&dxh, g_xh);
    cudaGetSymbolAddress((void**)&dqh, g_qh);
    cudaGetSymbolAddress((void**)&dkh, g_kh);
    cudaGetSymbolAddress((void**)&dvh, g_vh);
    cudaGetSymbolAddress((void**)&doh, g_oh);
    cudaGetSymbolAddress((void**)&dwh, g_wh);

    cudaFuncSetAttribute(gemm_f16_kernel,
                         cudaFuncAttributeMaxDynamicSharedMemorySize,
                         GEMM_SMEM_BYTES);
    cudaFuncSetAttribute(flash_f16_kernel,
                         cudaFuncAttributeMaxDynamicSharedMemorySize,
                         FLASH_SMEM_BYTES);

    // 0. fp32 -> fp16 conversions (x and the four weight matrices)
    {
        int nx4 = (S_TOK * DIM) / 4;
        int nw4 = (DIM * DIM) / 4;
        cvt_f16_kernel<<<(nx4 + 255) / 256, 256>>>(x,  dxh, nx4);
        cvt_f16_kernel<<<(nw4 + 255) / 256, 256>>>(Wq, dwh + 0 * (size_t)DIM * DIM, nw4);
        cvt_f16_kernel<<<(nw4 + 255) / 256, 256>>>(Wk, dwh + 1 * (size_t)DIM * DIM, nw4);
        cvt_f16_kernel<<<(nw4 + 255) / 256, 256>>>(Wv, dwh + 2 * (size_t)DIM * DIM, nw4);
        cvt_f16_kernel<<<(nw4 + 255) / 256, 256>>>(Wo, dwh + 3 * (size_t)DIM * DIM, nw4);
    }

    // 1. RoPE tables
    rope_table_kernel<<<(S_TOK * HD_HALF + 255) / 256, 256>>>(freqs);

    // 2. q/k/v projections (fp16 mma): q,k -> fp32 (for norm); v -> fp16
    dim3 ggrid(DIM / GBN, S_TOK / GBM);
    gemm_f16_kernel<<<ggrid, 256, GEMM_SMEM_BYTES>>>(
        dxh, dwh + 0 * (size_t)DIM * DIM, bq, dq, nullptr, 0, S_TOK, DIM, DIM);
    gemm_f16_kernel<<<ggrid, 256, GEMM_SMEM_BYTES>>>(
        dxh, dwh + 1 * (size_t)DIM * DIM, bk, dk, nullptr, 0, S_TOK, DIM, DIM);
    gemm_f16_kernel<<<ggrid, 256, GEMM_SMEM_BYTES>>>(
        dxh, dwh + 2 * (size_t)DIM * DIM, bv, nullptr, dvh, 1, S_TOK, DIM, DIM);

    // 3. RMSNorm + RoPE (fp32 in, fp16 out)
    norm_rope_kernel<<<S_TOK, 256>>>(gq, gk);

    // 4. flash attention (fp16 mma)
    dim3 fgrid(S_TOK / FQ, HEADS);
    flash_f16_kernel<<<fgrid, 256, FLASH_SMEM_BYTES>>>();

    // 5. output projection -> d_out (fp32)
    gemm_f16_kernel<<<ggrid, 256, GEMM_SMEM_BYTES>>>(
        doh, dwh + 3 * (size_t)DIM * DIM, bo, out, nullptr, 0, S_TOK, DIM, DIM);

    (void)in_sizes; (void)n_in; (void)out_size;
}